// round 2
// baseline (speedup 1.0000x reference)
#include <cuda_runtime.h>
#include <cstdint>

#define B_   16384
#define F_   1024
#define H_   64
#define D_   256
#define TE_  4
#define CE_  4
#define NH_  256   // TE_*H_ flattened hidden per group

typedef unsigned long long ull;

// ---------------- scratch (device globals: allocation-free) ----------------
__device__ float g_H[3ull * B_ * NH_];        // relu(x@W1+b1) per group, [3][B][256]
__device__ float g_logits[3ull * B_ * 16];    // raw gate logits, padded to 16

// ---------------- f32x2 helpers ----------------
__device__ __forceinline__ ull pack2(float lo, float hi) {
    ull r; asm("mov.b64 %0, {%1, %2};" : "=l"(r) : "f"(lo), "f"(hi)); return r;
}
__device__ __forceinline__ void unpack2(ull p, float& lo, float& hi) {
    asm("mov.b64 {%0, %1}, %2;" : "=f"(lo), "=f"(hi) : "l"(p));
}
__device__ __forceinline__ ull ffma2(ull a, ull b, ull c) {
    ull d; asm("fma.rn.f32x2 %0, %1, %2, %3;" : "=l"(d) : "l"(a), "l"(b), "l"(c));
    return d;
}

// ============================================================================
// Kernel 1: layer-1 GEMM per group:  H[g] = relu(x_g @ W1cat_g + b1_g)
//   x: [B,F]  W1: [4,F,64] (column n=(e=n>>6, h=n&63))  b1: [4,64] = flat [256]
//   Tile: BM=128, BN=128, BK=8; 256 threads; per-thread 8x8 via f32x2.
//   grid: (2, B/128, 3)
// ============================================================================
__global__ __launch_bounds__(256)
void gemm1_kernel(const float* __restrict__ xA, const float* __restrict__ xS,
                  const float* __restrict__ xB,
                  const float* __restrict__ W1A, const float* __restrict__ W1S,
                  const float* __restrict__ W1B,
                  const float* __restrict__ b1A, const float* __restrict__ b1S,
                  const float* __restrict__ b1B)
{
    __shared__ __align__(16) float As[8][132];
    __shared__ __align__(16) float Bs[8][128];

    const int g = blockIdx.z;
    const float* xs[3]  = {xA, xS, xB};
    const float* w1s[3] = {W1A, W1S, W1B};
    const float* b1s[3] = {b1A, b1S, b1B};
    const float* __restrict__ x  = xs[g];
    const float* __restrict__ W1 = w1s[g];
    const float* __restrict__ b1 = b1s[g];
    float* __restrict__ Hout = g_H + (size_t)g * B_ * NH_;

    const int tid = threadIdx.x;
    const int tx = tid & 15, ty = tid >> 4;
    const int m0 = blockIdx.y * 128;
    const int n0 = blockIdx.x * 128;

    // A-tile load mapping: 128x8 floats, one float4/thread
    const int arow = tid >> 1;
    const int akc  = (tid & 1) * 4;
    const float* asrc = x + (size_t)(m0 + arow) * F_ + akc;

    // B-tile load mapping: 8x128, one float4/thread
    const int brow = tid >> 5;
    const int bnc  = (tid & 31) * 4;
    const int ng   = n0 + bnc;
    const float* bsrc = W1 + ((size_t)(ng >> 6) << 16) + (ng & 63); // + k*64

    ull acc[8][4];
#pragma unroll
    for (int i = 0; i < 8; i++)
#pragma unroll
        for (int j = 0; j < 4; j++) acc[i][j] = 0ull;

    for (int k0 = 0; k0 < F_; k0 += 8) {
        float4 av = *(const float4*)(asrc + k0);
        As[akc + 0][arow] = av.x;
        As[akc + 1][arow] = av.y;
        As[akc + 2][arow] = av.z;
        As[akc + 3][arow] = av.w;
        float4 bv = *(const float4*)(bsrc + (size_t)(k0 + brow) * 64);
        *(float4*)&Bs[brow][bnc] = bv;
        __syncthreads();

#pragma unroll
        for (int kk = 0; kk < 8; kk++) {
            float4 a0 = *(const float4*)&As[kk][ty * 8];
            float4 a1 = *(const float4*)&As[kk][ty * 8 + 4];
            ull pa[8];
            pa[0] = pack2(a0.x, a0.x); pa[1] = pack2(a0.y, a0.y);
            pa[2] = pack2(a0.z, a0.z); pa[3] = pack2(a0.w, a0.w);
            pa[4] = pack2(a1.x, a1.x); pa[5] = pack2(a1.y, a1.y);
            pa[6] = pack2(a1.z, a1.z); pa[7] = pack2(a1.w, a1.w);
            ull pb[4];
#pragma unroll
            for (int j = 0; j < 4; j++)
                pb[j] = *(const ull*)&Bs[kk][tx * 8 + 2 * j];
#pragma unroll
            for (int i = 0; i < 8; i++)
#pragma unroll
                for (int j = 0; j < 4; j++)
                    acc[i][j] = ffma2(pa[i], pb[j], acc[i][j]);
        }
        __syncthreads();
    }

    // epilogue: bias + relu, write H
#pragma unroll
    for (int i = 0; i < 8; i++) {
        const int row = m0 + ty * 8 + i;
        float* op = Hout + (size_t)row * NH_ + n0 + tx * 8;
#pragma unroll
        for (int j = 0; j < 4; j++) {
            float lo, hi;
            unpack2(acc[i][j], lo, hi);
            const int n = n0 + tx * 8 + 2 * j;
            lo = fmaxf(lo + __ldg(&b1[n]),     0.f);
            hi = fmaxf(hi + __ldg(&b1[n + 1]), 0.f);
            float2 o; o.x = lo; o.y = hi;
            *(float2*)(op + 2 * j) = o;
        }
    }
}

// ============================================================================
// Kernel 1b: gate logits: L[g] = x_g @ Wg + bg   (ncols = 8, 12, 8)
//   128 rows/block, 128 threads (one row each). grid: (B/128, 3)
// ============================================================================
__global__ __launch_bounds__(128)
void gate_kernel(const float* __restrict__ xA, const float* __restrict__ xS,
                 const float* __restrict__ xB,
                 const float* __restrict__ WgA, const float* __restrict__ WgS,
                 const float* __restrict__ WgB,
                 const float* __restrict__ bgA, const float* __restrict__ bgS,
                 const float* __restrict__ bgB)
{
    __shared__ __align__(16) float xsm[8][132];
    __shared__ float wgs[8][16];

    const int g = blockIdx.y;
    const float* xsel[3] = {xA, xS, xB};
    const float* wsel[3] = {WgA, WgS, WgB};
    const float* bsel[3] = {bgA, bgS, bgB};
    const int ncol_tab[3] = {TE_ + CE_, 2 * TE_ + CE_, TE_ + CE_}; // 8,12,8
    const float* __restrict__ x  = xsel[g];
    const float* __restrict__ Wg = wsel[g];
    const float* __restrict__ bg = bsel[g];
    const int ncols = ncol_tab[g];

    const int tid = threadIdx.x;
    const int m0 = blockIdx.x * 128;

    float lacc[16];
#pragma unroll
    for (int n = 0; n < 16; n++) lacc[n] = 0.f;

    const int arow = tid >> 1;
    const int akc  = (tid & 1) * 4;
    const int wk = tid >> 4, wn = tid & 15;

    for (int k0 = 0; k0 < F_; k0 += 8) {
        // coalesced x tile: two 64-row halves
#pragma unroll
        for (int h = 0; h < 2; h++) {
            const int r = h * 64 + arow;
            float4 v = *(const float4*)(x + (size_t)(m0 + r) * F_ + k0 + akc);
            xsm[akc + 0][r] = v.x;
            xsm[akc + 1][r] = v.y;
            xsm[akc + 2][r] = v.z;
            xsm[akc + 3][r] = v.w;
        }
        wgs[wk][wn] = (wn < ncols) ? Wg[(size_t)(k0 + wk) * ncols + wn] : 0.f;
        __syncthreads();

#pragma unroll
        for (int kk = 0; kk < 8; kk++) {
            const float a = xsm[kk][tid];
#pragma unroll
            for (int n = 0; n < 16; n++) lacc[n] += a * wgs[kk][n];
        }
        __syncthreads();
    }

    float* lp = g_logits + ((size_t)g * B_ + (m0 + tid)) * 16;
    for (int n = 0; n < ncols; n++) lp[n] = lacc[n] + bg[n];
}

// ---------------- tiny softmax into gate smem ----------------
__device__ __forceinline__ void softmax_store(const float* lp, int n, float* dst)
{
    float v[12];
    float mx = -1e30f;
    for (int i = 0; i < n; i++) { v[i] = lp[i]; mx = fmaxf(mx, v[i]); }
    float s = 0.f;
    for (int i = 0; i < n; i++) { v[i] = expf(v[i] - mx); s += v[i]; }
    const float inv = 1.f / s;
    for (int i = 0; i < n; i++) dst[i] = v[i] * inv;
}

// ============================================================================
// Kernel 2: fused layer-2 + softmax gates + 3-way combine.
//   For each (g,e) of 12: E = relu(H_tile @ W2[g][e] + b2), accumulate into
//   outA/outS/outB with softmaxed gates. Tile: 64 rows x 64 d-cols.
//   grid: (D/64=4, B/64=256), 256 threads, per-thread 4x4 via f32x2.
//   gate smem layout per row: [0:8)=gA, [8:20)=gS, [20:28)=gB
// ============================================================================
__global__ __launch_bounds__(256)
void fuse2_kernel(const float* __restrict__ W2A, const float* __restrict__ b2A,
                  const float* __restrict__ W2S, const float* __restrict__ b2S,
                  const float* __restrict__ W2B, const float* __restrict__ b2B,
                  float* __restrict__ out)
{
    __shared__ __align__(16) float Ahs[64][68];
    __shared__ __align__(16) float Bhs[64][64];
    __shared__ float gs[64][32];

    const float* W2[3] = {W2A, W2S, W2B};
    const float* b2[3] = {b2A, b2S, b2B};

    const int tid = threadIdx.x;
    const int tx = tid & 15, ty = tid >> 4;
    const int d0 = blockIdx.x * 64;
    const int m0 = blockIdx.y * 64;

    if (tid < 64) {
        const int row = m0 + tid;
        softmax_store(g_logits + ((size_t)0 * B_ + row) * 16,  8, &gs[tid][0]);
        softmax_store(g_logits + ((size_t)1 * B_ + row) * 16, 12, &gs[tid][8]);
        softmax_store(g_logits + ((size_t)2 * B_ + row) * 16,  8, &gs[tid][20]);
    }
    __syncthreads();

    float oA[4][4], oS[4][4], oB[4][4];
#pragma unroll
    for (int i = 0; i < 4; i++)
#pragma unroll
        for (int j = 0; j < 4; j++) { oA[i][j] = 0.f; oS[i][j] = 0.f; oB[i][j] = 0.f; }

    const int lr  = tid >> 2;
    const int lc0 = (tid & 3) * 4;

#pragma unroll
    for (int g = 0; g < 3; g++) {
        const float* __restrict__ Hp = g_H + (size_t)g * B_ * NH_;
#pragma unroll
        for (int e = 0; e < TE_; e++) {
            // load H tile (transposed into Ahs[k][m]) and W2 tile (Bhs[k][d])
#pragma unroll
            for (int c = 0; c < 4; c++) {
                const int col = lc0 + c * 16;
                float4 v = *(const float4*)(Hp + (size_t)(m0 + lr) * NH_ + e * 64 + col);
                Ahs[col + 0][lr] = v.x;
                Ahs[col + 1][lr] = v.y;
                Ahs[col + 2][lr] = v.z;
                Ahs[col + 3][lr] = v.w;
                float4 w = *(const float4*)(W2[g] + ((size_t)e * 64 + lr) * D_ + d0 + col);
                *(float4*)&Bhs[lr][col] = w;
            }
            __syncthreads();

            ull accp[4][2];
#pragma unroll
            for (int i = 0; i < 4; i++) { accp[i][0] = 0ull; accp[i][1] = 0ull; }

#pragma unroll 8
            for (int kk = 0; kk < 64; kk++) {
                float4 a = *(const float4*)&Ahs[kk][ty * 4];
                ull pa0 = pack2(a.x, a.x), pa1 = pack2(a.y, a.y);
                ull pa2 = pack2(a.z, a.z), pa3 = pack2(a.w, a.w);
                ull pb0 = *(const ull*)&Bhs[kk][tx * 4];
                ull pb1 = *(const ull*)&Bhs[kk][tx * 4 + 2];
                accp[0][0] = ffma2(pa0, pb0, accp[0][0]);
                accp[0][1] = ffma2(pa0, pb1, accp[0][1]);
                accp[1][0] = ffma2(pa1, pb0, accp[1][0]);
                accp[1][1] = ffma2(pa1, pb1, accp[1][1]);
                accp[2][0] = ffma2(pa2, pb0, accp[2][0]);
                accp[2][1] = ffma2(pa2, pb1, accp[2][1]);
                accp[3][0] = ffma2(pa3, pb0, accp[3][0]);
                accp[3][1] = ffma2(pa3, pb1, accp[3][1]);
            }
            __syncthreads();

            // epilogue: bias + relu + gated accumulation
            const float* bb = b2[g] + e * D_ + d0 + tx * 4;
            float bc[4];
#pragma unroll
            for (int j = 0; j < 4; j++) bc[j] = __ldg(bb + j);

#pragma unroll
            for (int i = 0; i < 4; i++) {
                const int rl = ty * 4 + i;
                float wA = 0.f, wS = 0.f, wB = 0.f;
                if (g == 0)      { wA = gs[rl][e];      wS = gs[rl][8 + e]; }
                else if (g == 1) { wA = gs[rl][4 + e];  wS = gs[rl][12 + e]; wB = gs[rl][24 + e]; }
                else             { wS = gs[rl][16 + e]; wB = gs[rl][20 + e]; }
#pragma unroll
                for (int jp = 0; jp < 2; jp++) {
                    float lo, hi;
                    unpack2(accp[i][jp], lo, hi);
                    const float v0 = fmaxf(lo + bc[2 * jp],     0.f);
                    const float v1 = fmaxf(hi + bc[2 * jp + 1], 0.f);
                    if (g == 0) {
                        oA[i][2 * jp]     += wA * v0;  oA[i][2 * jp + 1] += wA * v1;
                        oS[i][2 * jp]     += wS * v0;  oS[i][2 * jp + 1] += wS * v1;
                    } else if (g == 1) {
                        oA[i][2 * jp]     += wA * v0;  oA[i][2 * jp + 1] += wA * v1;
                        oS[i][2 * jp]     += wS * v0;  oS[i][2 * jp + 1] += wS * v1;
                        oB[i][2 * jp]     += wB * v0;  oB[i][2 * jp + 1] += wB * v1;
                    } else {
                        oS[i][2 * jp]     += wS * v0;  oS[i][2 * jp + 1] += wS * v1;
                        oB[i][2 * jp]     += wB * v0;  oB[i][2 * jp + 1] += wB * v1;
                    }
                }
            }
        }
    }

    // write outputs: [outA | outS | outB], each [B, 256]
#pragma unroll
    for (int i = 0; i < 4; i++) {
        const size_t base = (size_t)(m0 + ty * 4 + i) * D_ + d0 + tx * 4;
        float4 a; a.x = oA[i][0]; a.y = oA[i][1]; a.z = oA[i][2]; a.w = oA[i][3];
        float4 s; s.x = oS[i][0]; s.y = oS[i][1]; s.z = oS[i][2]; s.w = oS[i][3];
        float4 b; b.x = oB[i][0]; b.y = oB[i][1]; b.z = oB[i][2]; b.w = oB[i][3];
        *(float4*)(out + base)                        = a;
        *(float4*)(out + (size_t)B_ * D_ + base)      = s;
        *(float4*)(out + (size_t)2 * B_ * D_ + base)  = b;
    }
}

// ============================================================================
// launcher
// ============================================================================
extern "C" void kernel_launch(void* const* d_in, const int* in_sizes, int n_in,
                              void* d_out, int out_size)
{
    const float* xA  = (const float*)d_in[0];
    const float* xS  = (const float*)d_in[1];
    const float* xB  = (const float*)d_in[2];
    const float* W1A = (const float*)d_in[3];
    const float* b1A = (const float*)d_in[4];
    const float* W2A = (const float*)d_in[5];
    const float* b2A = (const float*)d_in[6];
    const float* W1S = (const float*)d_in[7];
    const float* b1S = (const float*)d_in[8];
    const float* W2S = (const float*)d_in[9];
    const float* b2S = (const float*)d_in[10];
    const float* W1B = (const float*)d_in[11];
    const float* b1B = (const float*)d_in[12];
    const float* W2B = (const float*)d_in[13];
    const float* b2B = (const float*)d_in[14];
    const float* WgA = (const float*)d_in[15];
    const float* bgA = (const float*)d_in[16];
    const float* WgB = (const float*)d_in[17];   // NOTE: WgB before WgS (dict order)
    const float* bgB = (const float*)d_in[18];
    const float* WgS = (const float*)d_in[19];
    const float* bgS = (const float*)d_in[20];
    float* out = (float*)d_out;

    dim3 g1(NH_ / 128, B_ / 128, 3);
    gemm1_kernel<<<g1, 256>>>(xA, xS, xB, W1A, W1S, W1B, b1A, b1S, b1B);

    dim3 gg(B_ / 128, 3);
    gate_kernel<<<gg, 128>>>(xA, xS, xB, WgA, WgS, WgB, bgA, bgS, bgB);

    dim3 g2(D_ / 64, B_ / 64);
    fuse2_kernel<<<g2, 256>>>(W2A, b2A, W2S, b2S, W2B, b2B, out);
}

// round 4
// speedup vs baseline: 1.8061x; 1.8061x over previous
#include <cuda_runtime.h>
#include <cuda_bf16.h>
#include <cstdint>

#define B_   16384
#define F_   1024
#define D_   256
#define TE_  4
#define CE_  4
#define NH_  256

typedef unsigned long long ull;

// ---------------- scratch (device globals) ----------------
__device__ __nv_bfloat16 g_Hhi[3ull * B_ * NH_];
__device__ __nv_bfloat16 g_Hlo[3ull * B_ * NH_];
__device__ float g_logits[3ull * B_ * 16];
__device__ __nv_bfloat16 g_W1hi[3ull * 256 * 1024];   // [g][n=e*64+h][k]
__device__ __nv_bfloat16 g_W1lo[3ull * 256 * 1024];
__device__ __nv_bfloat16 g_W2hi[12ull * 256 * 64];    // [(g*4+e)][d][k]
__device__ __nv_bfloat16 g_W2lo[12ull * 256 * 64];

// ---------------- helpers ----------------
__device__ __forceinline__ uint32_t smem_u32(const void* p) {
    uint32_t a;
    asm("{ .reg .u64 t; cvta.to.shared.u64 t, %1; cvt.u32.u64 %0, t; }" : "=r"(a) : "l"(p));
    return a;
}
__device__ __forceinline__ void splitpair(float a, float b, uint32_t& h, uint32_t& l) {
    __nv_bfloat16 ha = __float2bfloat16_rn(a), hb = __float2bfloat16_rn(b);
    float ra = a - __bfloat162float(ha), rb = b - __bfloat162float(hb);
    __nv_bfloat162 hv; hv.x = ha; hv.y = hb;
    __nv_bfloat162 lv; lv.x = __float2bfloat16_rn(ra); lv.y = __float2bfloat16_rn(rb);
    h = *(uint32_t*)&hv; l = *(uint32_t*)&lv;
}
__device__ __forceinline__ void ldsm_x4(uint32_t* r, uint32_t addr) {
    asm volatile("ldmatrix.sync.aligned.m8n8.x4.shared.b16 {%0,%1,%2,%3}, [%4];"
                 : "=r"(r[0]), "=r"(r[1]), "=r"(r[2]), "=r"(r[3]) : "r"(addr));
}
__device__ __forceinline__ void mma_bf16(float* c, const uint32_t* a, const uint32_t* b) {
    asm volatile(
        "mma.sync.aligned.m16n8k16.row.col.f32.bf16.bf16.f32 "
        "{%0,%1,%2,%3}, {%4,%5,%6,%7}, {%8,%9}, {%0,%1,%2,%3};"
        : "+f"(c[0]), "+f"(c[1]), "+f"(c[2]), "+f"(c[3])
        : "r"(a[0]), "r"(a[1]), "r"(a[2]), "r"(a[3]), "r"(b[0]), "r"(b[1]));
}
#define CP_ASYNC16(dst, src) \
    asm volatile("cp.async.ca.shared.global [%0], [%1], 16;" :: "r"(dst), "l"(src))
#define CP_COMMIT()  asm volatile("cp.async.commit_group;" ::: "memory")
#define CP_WAIT0()   asm volatile("cp.async.wait_group 0;" ::: "memory")

// ============================================================================
// Repack W1 [4][1024][64] f32 -> [256 n][1024 k] bf16 hi/lo
// ============================================================================
__global__ __launch_bounds__(256)
void repack_w1(const float* __restrict__ W1A, const float* __restrict__ W1S,
               const float* __restrict__ W1B)
{
    __shared__ float ts[64][65];
    const int g = blockIdx.z, e = blockIdx.y, kb = blockIdx.x;
    const float* sel[3] = {W1A, W1S, W1B};
    const float* W = sel[g] + ((size_t)e * 1024 + kb * 64) * 64;  // [64 k][64 h]

    const int tid = threadIdx.x;
    const int r = tid >> 2, q = tid & 3;
#pragma unroll
    for (int j = 0; j < 4; j++) {
        float4 v = *(const float4*)(W + r * 64 + q * 16 + j * 4);
        ts[r][q * 16 + j * 4 + 0] = v.x;
        ts[r][q * 16 + j * 4 + 1] = v.y;
        ts[r][q * 16 + j * 4 + 2] = v.z;
        ts[r][q * 16 + j * 4 + 3] = v.w;
    }
    __syncthreads();

    const int h = tid >> 2;
    const size_t outbase = ((size_t)g * 256 + e * 64 + h) * 1024 + kb * 64 + q * 16;
#pragma unroll
    for (int jj = 0; jj < 2; jj++) {
        uint32_t hp[4], lp[4];
#pragma unroll
        for (int p = 0; p < 4; p++) {
            const int k = q * 16 + jj * 8 + p * 2;
            splitpair(ts[k][h], ts[k + 1][h], hp[p], lp[p]);
        }
        *(uint4*)(g_W1hi + outbase + jj * 8) = make_uint4(hp[0], hp[1], hp[2], hp[3]);
        *(uint4*)(g_W1lo + outbase + jj * 8) = make_uint4(lp[0], lp[1], lp[2], lp[3]);
    }
}

// ============================================================================
// Repack W2 [4][64 k][256 d] f32 -> [(g*4+e)][256 d][64 k] bf16 hi/lo
// ============================================================================
__global__ __launch_bounds__(256)
void repack_w2(const float* __restrict__ W2A, const float* __restrict__ W2S,
               const float* __restrict__ W2B)
{
    __shared__ float ts[64][65];
    const int g = blockIdx.z, e = blockIdx.y, dc = blockIdx.x;
    const float* sel[3] = {W2A, W2S, W2B};
    const float* W = sel[g] + (size_t)e * 64 * 256 + dc * 64;  // [k][d] slice

    const int tid = threadIdx.x;
    const int r = tid >> 2, q = tid & 3;  // r = k row
#pragma unroll
    for (int j = 0; j < 4; j++) {
        float4 v = *(const float4*)(W + (size_t)r * 256 + q * 16 + j * 4);
        ts[r][q * 16 + j * 4 + 0] = v.x;
        ts[r][q * 16 + j * 4 + 1] = v.y;
        ts[r][q * 16 + j * 4 + 2] = v.z;
        ts[r][q * 16 + j * 4 + 3] = v.w;
    }
    __syncthreads();

    const int d = tid >> 2;
    const size_t outbase = ((size_t)(g * 4 + e) * 256 + dc * 64 + d) * 64 + q * 16;
#pragma unroll
    for (int jj = 0; jj < 2; jj++) {
        uint32_t hp[4], lp[4];
#pragma unroll
        for (int p = 0; p < 4; p++) {
            const int k = q * 16 + jj * 8 + p * 2;
            splitpair(ts[k][d], ts[k + 1][d], hp[p], lp[p]);
        }
        *(uint4*)(g_W2hi + outbase + jj * 8) = make_uint4(hp[0], hp[1], hp[2], hp[3]);
        *(uint4*)(g_W2lo + outbase + jj * 8) = make_uint4(lp[0], lp[1], lp[2], lp[3]);
    }
}

// ============================================================================
// gemm1: H[g] = relu(x_g @ W1cat + b1), HMMA bf16 hi/lo split.
// CTA 128m x 128n, BK=32, 8 warps (4x2), warp tile 32x64.
// Output stored directly as bf16 hi/lo into g_Hhi/g_Hlo.
// ============================================================================
#define SA      40                       // smem row stride (elems)
#define AH_OFF  0
#define AL_OFF  10240
#define BH_OFF  20480
#define BL_OFF  30720
#define STAGE1  40960
#define SMEM_G1 (2 * STAGE1)             // 80 KB

__global__ __launch_bounds__(256, 1)
void gemm1_hmma(const float* __restrict__ xA, const float* __restrict__ xS,
                const float* __restrict__ xB,
                const float* __restrict__ b1A, const float* __restrict__ b1S,
                const float* __restrict__ b1B)
{
    extern __shared__ char sm[];
    const uint32_t smb = smem_u32(sm);
    const int tid = threadIdx.x;
    const int wid = tid >> 5, lane = tid & 31;
    const int warp_m = wid & 3, warp_n = wid >> 2;

    const int g = blockIdx.z;
    const int m0 = blockIdx.y * 128;
    const int n0 = blockIdx.x * 128;
    const float* xsel[3] = {xA, xS, xB};
    const float* bsel[3] = {b1A, b1S, b1B};
    const float* __restrict__ x  = xsel[g];
    const float* __restrict__ b1 = bsel[g];

    // A loader: row = tid>>1, seg = (tid&1)*16 (16 floats)
    const int arow = tid >> 1, aseg = (tid & 1) * 16;
    const float* aptr = x + (size_t)(m0 + arow) * F_ + aseg;
    const uint32_t a_off = (uint32_t)(arow * SA + aseg) * 2;  // byte off in buf

    // B loader: row n = tid>>1, half = (tid&1)*16 (16 bf16 = 2x16B)
    const int brow = tid >> 1, bhalf = (tid & 1) * 16;
    const __nv_bfloat16* bhp = g_W1hi + ((size_t)(g * 256 + n0 + brow)) * 1024 + bhalf;
    const __nv_bfloat16* blp = g_W1lo + ((size_t)(g * 256 + n0 + brow)) * 1024 + bhalf;
    const uint32_t b_off = (uint32_t)(brow * SA + bhalf) * 2;

    float acc[2][8][4];
#pragma unroll
    for (int i = 0; i < 2; i++)
#pragma unroll
        for (int j = 0; j < 8; j++)
#pragma unroll
            for (int r = 0; r < 4; r++) acc[i][j][r] = 0.f;

    // ldmatrix addresses (stage-relative byte offsets)
    uint32_t a_lds[2], b_lds[4];
#pragma unroll
    for (int mi = 0; mi < 2; mi++)
        a_lds[mi] = (uint32_t)(((warp_m * 32 + mi * 16 + (lane & 15)) * SA
                                + ((lane >> 4) << 3)) * 2);
#pragma unroll
    for (int np = 0; np < 4; np++)
        b_lds[np] = (uint32_t)(((warp_n * 64 + np * 16 + (lane & 7) + ((lane >> 4) << 3)) * SA
                                + (((lane >> 3) & 1) << 3)) * 2);

    // ---- prologue: stage 0 ----
    {
        float4 av[4];
#pragma unroll
        for (int j = 0; j < 4; j++) av[j] = *(const float4*)(aptr + j * 4);
        uint32_t h[8], l[8];
#pragma unroll
        for (int j = 0; j < 4; j++) {
            splitpair(av[j].x, av[j].y, h[j * 2], l[j * 2]);
            splitpair(av[j].z, av[j].w, h[j * 2 + 1], l[j * 2 + 1]);
        }
        *(uint4*)(sm + AH_OFF + a_off)      = make_uint4(h[0], h[1], h[2], h[3]);
        *(uint4*)(sm + AH_OFF + a_off + 16) = make_uint4(h[4], h[5], h[6], h[7]);
        *(uint4*)(sm + AL_OFF + a_off)      = make_uint4(l[0], l[1], l[2], l[3]);
        *(uint4*)(sm + AL_OFF + a_off + 16) = make_uint4(l[4], l[5], l[6], l[7]);
        CP_ASYNC16(smb + BH_OFF + b_off,      bhp);
        CP_ASYNC16(smb + BH_OFF + b_off + 16, bhp + 8);
        CP_ASYNC16(smb + BL_OFF + b_off,      blp);
        CP_ASYNC16(smb + BL_OFF + b_off + 16, blp + 8);
        CP_COMMIT();
    }

    float4 av[4];
    for (int c = 0; c < 32; c++) {
        const int s = c & 1;
        CP_WAIT0();
        __syncthreads();

        const bool more = (c + 1 < 32);
        if (more) {
            const int sn = s ^ 1;
#pragma unroll
            for (int j = 0; j < 4; j++)
                av[j] = *(const float4*)(aptr + (c + 1) * 32 + j * 4);
            const uint32_t bb = smb + sn * STAGE1;
            CP_ASYNC16(bb + BH_OFF + b_off,      bhp + (c + 1) * 32);
            CP_ASYNC16(bb + BH_OFF + b_off + 16, bhp + (c + 1) * 32 + 8);
            CP_ASYNC16(bb + BL_OFF + b_off,      blp + (c + 1) * 32);
            CP_ASYNC16(bb + BL_OFF + b_off + 16, blp + (c + 1) * 32 + 8);
            CP_COMMIT();
        }

        // ---- compute stage s ----
        const uint32_t st = smb + s * STAGE1;
#pragma unroll
        for (int kk = 0; kk < 32; kk += 16) {
            uint32_t ah[2][4], al[2][4], bh[4][4], bl[4][4];
#pragma unroll
            for (int mi = 0; mi < 2; mi++) {
                ldsm_x4(ah[mi], st + AH_OFF + a_lds[mi] + kk * 2);
                ldsm_x4(al[mi], st + AL_OFF + a_lds[mi] + kk * 2);
            }
#pragma unroll
            for (int np = 0; np < 4; np++) {
                ldsm_x4(bh[np], st + BH_OFF + b_lds[np] + kk * 2);
                ldsm_x4(bl[np], st + BL_OFF + b_lds[np] + kk * 2);
            }
#pragma unroll
            for (int mi = 0; mi < 2; mi++)
#pragma unroll
                for (int np = 0; np < 4; np++)
#pragma unroll
                    for (int t = 0; t < 2; t++) {
                        float* cc = acc[mi][np * 2 + t];
                        mma_bf16(cc, ah[mi], &bh[np][t * 2]);
                        mma_bf16(cc, al[mi], &bh[np][t * 2]);
                        mma_bf16(cc, ah[mi], &bl[np][t * 2]);
                    }
        }

        if (more) {  // deferred A convert+store into stage s^1
            const int sn = s ^ 1;
            uint32_t h[8], l[8];
#pragma unroll
            for (int j = 0; j < 4; j++) {
                splitpair(av[j].x, av[j].y, h[j * 2], l[j * 2]);
                splitpair(av[j].z, av[j].w, h[j * 2 + 1], l[j * 2 + 1]);
            }
            char* bb = sm + sn * STAGE1;
            *(uint4*)(bb + AH_OFF + a_off)      = make_uint4(h[0], h[1], h[2], h[3]);
            *(uint4*)(bb + AH_OFF + a_off + 16) = make_uint4(h[4], h[5], h[6], h[7]);
            *(uint4*)(bb + AL_OFF + a_off)      = make_uint4(l[0], l[1], l[2], l[3]);
            *(uint4*)(bb + AL_OFF + a_off + 16) = make_uint4(l[4], l[5], l[6], l[7]);
        }
    }

    // ---- epilogue: bias + relu, split, store bf16 hi/lo ----
#pragma unroll
    for (int mi = 0; mi < 2; mi++) {
        const int r0 = m0 + warp_m * 32 + mi * 16 + (lane >> 2);
#pragma unroll
        for (int nj = 0; nj < 8; nj++) {
            const int col = n0 + warp_n * 64 + nj * 8 + (lane & 3) * 2;
            const float bz0 = __ldg(b1 + col), bz1 = __ldg(b1 + col + 1);
            float v00 = fmaxf(acc[mi][nj][0] + bz0, 0.f);
            float v01 = fmaxf(acc[mi][nj][1] + bz1, 0.f);
            float v10 = fmaxf(acc[mi][nj][2] + bz0, 0.f);
            float v11 = fmaxf(acc[mi][nj][3] + bz1, 0.f);
            uint32_t h0, l0, h1, l1;
            splitpair(v00, v01, h0, l0);
            splitpair(v10, v11, h1, l1);
            const size_t i0 = ((size_t)g * B_ + r0) * 256 + col;
            const size_t i1 = ((size_t)g * B_ + r0 + 8) * 256 + col;
            *(uint32_t*)(g_Hhi + i0) = h0;
            *(uint32_t*)(g_Hlo + i0) = l0;
            *(uint32_t*)(g_Hhi + i1) = h1;
            *(uint32_t*)(g_Hlo + i1) = l1;
        }
    }
}

// ============================================================================
// gate logits (SIMT, unchanged)
// ============================================================================
__global__ __launch_bounds__(128)
void gate_kernel(const float* __restrict__ xA, const float* __restrict__ xS,
                 const float* __restrict__ xB,
                 const float* __restrict__ WgA, const float* __restrict__ WgS,
                 const float* __restrict__ WgB,
                 const float* __restrict__ bgA, const float* __restrict__ bgS,
                 const float* __restrict__ bgB)
{
    __shared__ __align__(16) float xsm[8][132];
    __shared__ float wgs[8][16];

    const int g = blockIdx.y;
    const float* xsel[3] = {xA, xS, xB};
    const float* wsel[3] = {WgA, WgS, WgB};
    const float* bsel[3] = {bgA, bgS, bgB};
    const int ncol_tab[3] = {TE_ + CE_, 2 * TE_ + CE_, TE_ + CE_};
    const float* __restrict__ x  = xsel[g];
    const float* __restrict__ Wg = wsel[g];
    const float* __restrict__ bg = bsel[g];
    const int ncols = ncol_tab[g];

    const int tid = threadIdx.x;
    const int m0 = blockIdx.x * 128;

    float lacc[16];
#pragma unroll
    for (int n = 0; n < 16; n++) lacc[n] = 0.f;

    const int arow = tid >> 1;
    const int akc  = (tid & 1) * 4;
    const int wk = tid >> 4, wn = tid & 15;

    for (int k0 = 0; k0 < F_; k0 += 8) {
#pragma unroll
        for (int h = 0; h < 2; h++) {
            const int r = h * 64 + arow;
            float4 v = *(const float4*)(x + (size_t)(m0 + r) * F_ + k0 + akc);
            xsm[akc + 0][r] = v.x;
            xsm[akc + 1][r] = v.y;
            xsm[akc + 2][r] = v.z;
            xsm[akc + 3][r] = v.w;
        }
        wgs[wk][wn] = (wn < ncols) ? Wg[(size_t)(k0 + wk) * ncols + wn] : 0.f;
        __syncthreads();

#pragma unroll
        for (int kk = 0; kk < 8; kk++) {
            const float a = xsm[kk][tid];
#pragma unroll
            for (int n = 0; n < 16; n++) lacc[n] += a * wgs[kk][n];
        }
        __syncthreads();
    }

    float* lp = g_logits + ((size_t)g * B_ + (m0 + tid)) * 16;
    for (int n = 0; n < ncols; n++) lp[n] = lacc[n] + bg[n];
}

__device__ __forceinline__ void softmax_store(const float* lp, int n, float* dst)
{
    float v[12];
    float mx = -1e30f;
    for (int i = 0; i < n; i++) { v[i] = lp[i]; mx = fmaxf(mx, v[i]); }
    float s = 0.f;
    for (int i = 0; i < n; i++) { v[i] = expf(v[i] - mx); s += v[i]; }
    const float inv = 1.f / s;
    for (int i = 0; i < n; i++) dst[i] = v[i] * inv;
}

// ============================================================================
// fuse2: layer-2 HMMA + softmax gates + 3-way combine.
// CTA 128m x 64d. 8 warps (4x2), warp 32x32. 12 (g,e) stages double-buffered.
// A = H (bf16 hi/lo from gemm1), B = repacked W2 bf16 hi/lo.
// ============================================================================
#define SB2      72
#define F2_AH    0
#define F2_AL    18432
#define F2_BH    36864
#define F2_BL    46080
#define F2_STAGE 55296
#define F2_GS    (2 * F2_STAGE)          // gates: 128*32 floats = 16384 B
#define SMEM_F2  (F2_GS + 16384)         // 126976 B

__global__ __launch_bounds__(256, 1)
void fuse2_hmma(const float* __restrict__ b2A, const float* __restrict__ b2S,
                const float* __restrict__ b2B, float* __restrict__ out)
{
    extern __shared__ char sm[];
    const uint32_t smb = smem_u32(sm);
    float* gsm = (float*)(sm + F2_GS);

    const int tid = threadIdx.x;
    const int wid = tid >> 5, lane = tid & 31;
    const int warp_m = wid & 3, warp_n = wid >> 2;
    const int d0 = blockIdx.x * 64;
    const int m0 = blockIdx.y * 128;
    const float* bsel[3] = {b2A, b2S, b2B};

    // softmax gates for this row block
    if (tid < 128) {
        const int row = m0 + tid;
        softmax_store(g_logits + ((size_t)0 * B_ + row) * 16,  8, gsm + tid * 32);
        softmax_store(g_logits + ((size_t)1 * B_ + row) * 16, 12, gsm + tid * 32 + 8);
        softmax_store(g_logits + ((size_t)2 * B_ + row) * 16,  8, gsm + tid * 32 + 20);
    }

    // loader mappings
    const int alr = tid >> 1, alc = (tid & 1) * 32;     // A: 2 thr/row, 32 elems each
    const uint32_t a_off = (uint32_t)(alr * SB2 + alc) * 2;
    const int blr = tid >> 2, blc = (tid & 3) * 16;     // B: 4 thr/row, 16 elems each
    const uint32_t b_off = (uint32_t)(blr * SB2 + blc) * 2;

    // ldmatrix offsets
    uint32_t a_lds[2], b_lds[2];
#pragma unroll
    for (int mi = 0; mi < 2; mi++)
        a_lds[mi] = (uint32_t)(((warp_m * 32 + mi * 16 + (lane & 15)) * SB2
                                + ((lane >> 4) << 3)) * 2);
#pragma unroll
    for (int np = 0; np < 2; np++)
        b_lds[np] = (uint32_t)(((warp_n * 32 + np * 16 + (lane & 7) + ((lane >> 4) << 3)) * SB2
                                + (((lane >> 3) & 1) << 3)) * 2);

    // output accumulators
    float oA[2][4][4], oS[2][4][4], oB[2][4][4];
#pragma unroll
    for (int i = 0; i < 2; i++)
#pragma unroll
        for (int j = 0; j < 4; j++)
#pragma unroll
            for (int r = 0; r < 4; r++) { oA[i][j][r] = 0.f; oS[i][j][r] = 0.f; oB[i][j][r] = 0.f; }

    // stage loader
    auto load_stage = [&](int t, int s) {
        const int g = t >> 2, e = t & 3;
        const uint32_t bb = smb + s * F2_STAGE;
        const __nv_bfloat16* ah = g_Hhi + ((size_t)g * B_ + m0 + alr) * 256 + e * 64 + alc;
        const __nv_bfloat16* al = g_Hlo + ((size_t)g * B_ + m0 + alr) * 256 + e * 64 + alc;
#pragma unroll
        for (int j = 0; j < 4; j++) {
            CP_ASYNC16(bb + F2_AH + a_off + j * 16, ah + j * 8);
            CP_ASYNC16(bb + F2_AL + a_off + j * 16, al + j * 8);
        }
        const __nv_bfloat16* wh = g_W2hi + ((size_t)(g * 4 + t % 4) * 256 + d0 + blr) * 64 + blc;
        const __nv_bfloat16* wl = g_W2lo + ((size_t)(g * 4 + t % 4) * 256 + d0 + blr) * 64 + blc;
#pragma unroll
        for (int j = 0; j < 2; j++) {
            CP_ASYNC16(bb + F2_BH + b_off + j * 16, wh + j * 8);
            CP_ASYNC16(bb + F2_BL + b_off + j * 16, wl + j * 8);
        }
        CP_COMMIT();
    };

    load_stage(0, 0);

    for (int t = 0; t < 12; t++) {
        const int s = t & 1;
        const int g = t >> 2, e = t & 3;
        CP_WAIT0();
        __syncthreads();
        if (t + 1 < 12) load_stage(t + 1, s ^ 1);

        // ---- HMMA over K=64 ----
        float acc[2][4][4];
#pragma unroll
        for (int i = 0; i < 2; i++)
#pragma unroll
            for (int j = 0; j < 4; j++)
#pragma unroll
                for (int r = 0; r < 4; r++) acc[i][j][r] = 0.f;

        const uint32_t st = smb + s * F2_STAGE;
#pragma unroll
        for (int kk = 0; kk < 64; kk += 16) {
            uint32_t ah[2][4], al[2][4], bh[2][4], bl[2][4];
#pragma unroll
            for (int mi = 0; mi < 2; mi++) {
                ldsm_x4(ah[mi], st + F2_AH + a_lds[mi] + kk * 2);
                ldsm_x4(al[mi], st + F2_AL + a_lds[mi] + kk * 2);
            }
#pragma unroll
            for (int np = 0; np < 2; np++) {
                ldsm_x4(bh[np], st + F2_BH + b_lds[np] + kk * 2);
                ldsm_x4(bl[np], st + F2_BL + b_lds[np] + kk * 2);
            }
#pragma unroll
            for (int mi = 0; mi < 2; mi++)
#pragma unroll
                for (int np = 0; np < 2; np++)
#pragma unroll
                    for (int tt = 0; tt < 2; tt++) {
                        float* cc = acc[mi][np * 2 + tt];
                        mma_bf16(cc, ah[mi], &bh[np][tt * 2]);
                        mma_bf16(cc, al[mi], &bh[np][tt * 2]);
                        mma_bf16(cc, ah[mi], &bl[np][tt * 2]);
                    }
        }

        // ---- epilogue: bias + relu + gated accumulate ----
        const float* b2 = bsel[g];
#pragma unroll
        for (int mi = 0; mi < 2; mi++) {
            const int rl0 = warp_m * 32 + mi * 16 + (lane >> 2);
            const int rl1 = rl0 + 8;
            const float* gr0 = gsm + rl0 * 32;
            const float* gr1 = gsm + rl1 * 32;
            float wA0, wS0, wB0, wA1, wS1, wB1;
            if (g == 0) {
                wA0 = gr0[e];      wS0 = gr0[8 + e];  wB0 = 0.f;
                wA1 = gr1[e];      wS1 = gr1[8 + e];  wB1 = 0.f;
            } else if (g == 1) {
                wA0 = gr0[4 + e];  wS0 = gr0[12 + e]; wB0 = gr0[24 + e];
                wA1 = gr1[4 + e];  wS1 = gr1[12 + e]; wB1 = gr1[24 + e];
            } else {
                wA0 = 0.f;         wS0 = gr0[16 + e]; wB0 = gr0[20 + e];
                wA1 = 0.f;         wS1 = gr1[16 + e]; wB1 = gr1[20 + e];
            }
#pragma unroll
            for (int nj = 0; nj < 4; nj++) {
                const int dl = warp_n * 32 + nj * 8 + (lane & 3) * 2;
                const float bz0 = __ldg(b2 + e * D_ + d0 + dl);
                const float bz1 = __ldg(b2 + e * D_ + d0 + dl + 1);
                const float v00 = fmaxf(acc[mi][nj][0] + bz0, 0.f);
                const float v01 = fmaxf(acc[mi][nj][1] + bz1, 0.f);
                const float v10 = fmaxf(acc[mi][nj][2] + bz0, 0.f);
                const float v11 = fmaxf(acc[mi][nj][3] + bz1, 0.f);
                oA[mi][nj][0] += wA0 * v00;  oA[mi][nj][1] += wA0 * v01;
                oA[mi][nj][2] += wA1 * v10;  oA[mi][nj][3] += wA1 * v11;
                oS[mi][nj][0] += wS0 * v00;  oS[mi][nj][1] += wS0 * v01;
                oS[mi][nj][2] += wS1 * v10;  oS[mi][nj][3] += wS1 * v11;
                oB[mi][nj][0] += wB0 * v00;  oB[mi][nj][1] += wB0 * v01;
                oB[mi][nj][2] += wB1 * v10;  oB[mi][nj][3] += wB1 * v11;
            }
        }
    }

    // ---- final writes ----
#pragma unroll
    for (int mi = 0; mi < 2; mi++) {
        const int row = m0 + warp_m * 32 + mi * 16 + (lane >> 2);
#pragma unroll
        for (int nj = 0; nj < 4; nj++) {
            const int col = d0 + warp_n * 32 + nj * 8 + (lane & 3) * 2;
            const size_t i0 = (size_t)row * D_ + col;
            const size_t i1 = (size_t)(row + 8) * D_ + col;
            float2 a0 = make_float2(oA[mi][nj][0], oA[mi][nj][1]);
            float2 a1 = make_float2(oA[mi][nj][2], oA[mi][nj][3]);
            float2 s0 = make_float2(oS[mi][nj][0], oS[mi][nj][1]);
            float2 s1 = make_float2(oS[mi][nj][2], oS[mi][nj][3]);
            float2 bb0 = make_float2(oB[mi][nj][0], oB[mi][nj][1]);
            float2 bb1 = make_float2(oB[mi][nj][2], oB[mi][nj][3]);
            *(float2*)(out + i0) = a0;
            *(float2*)(out + i1) = a1;
            *(float2*)(out + (size_t)B_ * D_ + i0) = s0;
            *(float2*)(out + (size_t)B_ * D_ + i1) = s1;
            *(float2*)(out + (size_t)2 * B_ * D_ + i0) = bb0;
            *(float2*)(out + (size_t)2 * B_ * D_ + i1) = bb1;
        }
    }
}

// ============================================================================
// launcher
// ============================================================================
extern "C" void kernel_launch(void* const* d_in, const int* in_sizes, int n_in,
                              void* d_out, int out_size)
{
    const float* xA  = (const float*)d_in[0];
    const float* xS  = (const float*)d_in[1];
    const float* xB  = (const float*)d_in[2];
    const float* W1A = (const float*)d_in[3];
    const float* b1A = (const float*)d_in[4];
    const float* W2A = (const float*)d_in[5];
    const float* b2A = (const float*)d_in[6];
    const float* W1S = (const float*)d_in[7];
    const float* b1S = (const float*)d_in[8];
    const float* W2S = (const float*)d_in[9];
    const float* b2S = (const float*)d_in[10];
    const float* W1B = (const float*)d_in[11];
    const float* b1B = (const float*)d_in[12];
    const float* W2B = (const float*)d_in[13];
    const float* b2B = (const float*)d_in[14];
    const float* WgA = (const float*)d_in[15];
    const float* bgA = (const float*)d_in[16];
    const float* WgB = (const float*)d_in[17];   // WgB before WgS (dict order)
    const float* bgB = (const float*)d_in[18];
    const float* WgS = (const float*)d_in[19];
    const float* bgS = (const float*)d_in[20];
    float* out = (float*)d_out;

    cudaFuncSetAttribute(gemm1_hmma, cudaFuncAttributeMaxDynamicSharedMemorySize, SMEM_G1);
    cudaFuncSetAttribute(fuse2_hmma, cudaFuncAttributeMaxDynamicSharedMemorySize, SMEM_F2);

    dim3 gr1(16, 4, 3);
    repack_w1<<<gr1, 256>>>(W1A, W1S, W1B);
    dim3 gr2(4, 4, 3);
    repack_w2<<<gr2, 256>>>(W2A, W2S, W2B);

    dim3 g1(2, B_ / 128, 3);
    gemm1_hmma<<<g1, 256, SMEM_G1>>>(xA, xS, xB, b1A, b1S, b1B);

    dim3 gg(B_ / 128, 3);
    gate_kernel<<<gg, 128>>>(xA, xS, xB, WgA, WgS, WgB, bgA, bgS, bgB);

    dim3 g2(D_ / 64, B_ / 128);
    fuse2_hmma<<<g2, 256, SMEM_F2>>>(b2A, b2S, b2B, out);
}